// round 9
// baseline (speedup 1.0000x reference)
#include <cuda_runtime.h>
#include <cuda_bf16.h>
#include <math.h>

// Problem constants
#define B_    2
#define S_    1024
#define HID_  2048
#define HQ_   32
#define HKV_  8
#define HD_   64
#define MTOK  (B_ * S_)
#define NREP  (HQ_ / HKV_)

// Scratch
__device__ float g_q[MTOK * HID_];
__device__ float g_k[MTOK * HKV_ * HD_];
__device__ float g_v[MTOK * HKV_ * HD_];
__device__ float g_attn[MTOK * HID_];

__device__ __forceinline__ unsigned f2tf32(float x) {
    unsigned r;
    asm("cvt.rna.tf32.f32 %0, %1;" : "=r"(r) : "f"(x));
    return r;
}
__device__ __forceinline__ float f2tf32f(float x) {
    return __uint_as_float(f2tf32(x));
}

#define MMA_TF32(D, A, B0, B1)                                              \
    asm volatile(                                                           \
        "mma.sync.aligned.m16n8k8.row.col.f32.tf32.tf32.f32 "               \
        "{%0,%1,%2,%3}, {%4,%5,%6,%7}, {%8,%9}, {%0,%1,%2,%3};"             \
        : "+f"((D)[0]), "+f"((D)[1]), "+f"((D)[2]), "+f"((D)[3])            \
        : "r"((A)[0]), "r"((A)[1]), "r"((A)[2]), "r"((A)[3]),               \
          "r"(B0), "r"(B1))

#define CPA16(smu32, gptr) \
    asm volatile("cp.async.cg.shared.global [%0], [%1], 16;" :: "r"(smu32), "l"(gptr))
#define CPA_COMMIT() asm volatile("cp.async.commit_group;")
#define CPA_WAIT0()  asm volatile("cp.async.wait_group 0;" ::: "memory")
#define CPA_WAIT1()  asm volatile("cp.async.wait_group 1;" ::: "memory")

// ---------------------------------------------------------------------------
// tf32 tensor-core GEMM (unchanged math). V output (bx>=20) is rounded to
// tf32 bit pattern so attention can consume it raw.
// ---------------------------------------------------------------------------
#define BKT 32
#define SST 136

__global__ __launch_bounds__(256, 2)
void mma_gemm_qkv(const float* __restrict__ A,
                  const float* __restrict__ Wq, const float* __restrict__ Wk,
                  const float* __restrict__ Wv,
                  float* __restrict__ Cq, float* __restrict__ Ck,
                  float* __restrict__ Cv)
{
    __shared__ unsigned As[BKT][SST];
    __shared__ unsigned Bs[BKT][SST];

    const int bx = blockIdx.x;
    const int by = blockIdx.y;

    const float* Bp; float* Cp; int Nb, n0; bool cvtV = false;
    if (bx < 16)      { Bp = Wq; Cp = Cq; Nb = 2048; n0 = bx * 128; }
    else if (bx < 20) { Bp = Wk; Cp = Ck; Nb = 512;  n0 = (bx - 16) * 128; }
    else              { Bp = Wv; Cp = Cv; Nb = 512;  n0 = (bx - 20) * 128; cvtV = true; }

    const int tid  = threadIdx.x;
    const int wid  = tid >> 5;
    const int lane = tid & 31;
    const int wm   = wid >> 2;
    const int wn   = wid & 3;
    const int g    = lane >> 2;
    const int tg   = lane & 3;
    const int m0   = by * 128;

    float acc[4][4][4];
    #pragma unroll
    for (int mi = 0; mi < 4; mi++)
        #pragma unroll
        for (int ni = 0; ni < 4; ni++)
            #pragma unroll
            for (int c = 0; c < 4; c++) acc[mi][ni][c] = 0.f;

    const int arow  = tid >> 1;
    const int acol  = (tid & 1) * 16;
    const int bkrow = tid >> 3;
    const int bncol = (tid & 7) * 4;

    for (int k0 = 0; k0 < HID_; k0 += BKT) {
        #pragma unroll
        for (int j = 0; j < 4; j++) {
            float4 a4 = *(const float4*)(A + (size_t)(m0 + arow) * HID_ + k0 + acol + j * 4);
            As[acol + j * 4 + 0][arow] = f2tf32(a4.x);
            As[acol + j * 4 + 1][arow] = f2tf32(a4.y);
            As[acol + j * 4 + 2][arow] = f2tf32(a4.z);
            As[acol + j * 4 + 3][arow] = f2tf32(a4.w);
        }
        #pragma unroll
        for (int j = 0; j < 4; j++) {
            float4 b4 = *(const float4*)(Bp + (size_t)(k0 + bkrow) * Nb + n0 + bncol + j * 32);
            unsigned* dst = &Bs[bkrow][bncol + j * 32];
            dst[0] = f2tf32(b4.x);
            dst[1] = f2tf32(b4.y);
            dst[2] = f2tf32(b4.z);
            dst[3] = f2tf32(b4.w);
        }
        __syncthreads();

        #pragma unroll
        for (int ks = 0; ks < 4; ks++) {
            unsigned afr[4][4], bfr[4][2];
            #pragma unroll
            for (int mi = 0; mi < 4; mi++) {
                int mb = wm * 64 + mi * 16;
                afr[mi][0] = As[ks * 8 + tg    ][mb + g];
                afr[mi][1] = As[ks * 8 + tg    ][mb + g + 8];
                afr[mi][2] = As[ks * 8 + tg + 4][mb + g];
                afr[mi][3] = As[ks * 8 + tg + 4][mb + g + 8];
            }
            #pragma unroll
            for (int ni = 0; ni < 4; ni++) {
                int nb = wn * 32 + ni * 8;
                bfr[ni][0] = Bs[ks * 8 + tg    ][nb + g];
                bfr[ni][1] = Bs[ks * 8 + tg + 4][nb + g];
            }
            #pragma unroll
            for (int mi = 0; mi < 4; mi++)
                #pragma unroll
                for (int ni = 0; ni < 4; ni++)
                    MMA_TF32(acc[mi][ni], afr[mi], bfr[ni][0], bfr[ni][1]);
        }
        __syncthreads();
    }

    #pragma unroll
    for (int mi = 0; mi < 4; mi++) {
        int row0 = m0 + wm * 64 + mi * 16 + g;
        #pragma unroll
        for (int ni = 0; ni < 4; ni++) {
            int col = n0 + wn * 32 + ni * 8 + tg * 2;
            float v0 = acc[mi][ni][0], v1 = acc[mi][ni][1];
            float v2 = acc[mi][ni][2], v3 = acc[mi][ni][3];
            if (cvtV) {
                v0 = f2tf32f(v0); v1 = f2tf32f(v1);
                v2 = f2tf32f(v2); v3 = f2tf32f(v3);
            }
            *(float2*)(Cp + (size_t)row0 * Nb + col) = make_float2(v0, v1);
            *(float2*)(Cp + (size_t)(row0 + 8) * Nb + col) = make_float2(v2, v3);
        }
    }
}

// ---------------------------------------------------------------------------
// RoPE (in place), output rounded to tf32 bit pattern.
// ---------------------------------------------------------------------------
__global__ void rope_kernel(float* __restrict__ X,
                            const float* __restrict__ cosT,
                            const float* __restrict__ sinT,
                            int nheads)
{
    int idx = blockIdx.x * blockDim.x + threadIdx.x;
    int total = MTOK * nheads * 32;
    if (idx >= total) return;
    int d  = idx & 31;
    int hh = (idx >> 5) % nheads;
    int t  = idx / (32 * nheads);
    int s  = t & (S_ - 1);

    float c  = __ldg(cosT + s * HD_ + d);
    float sn = __ldg(sinT + s * HD_ + d);

    float* base = X + ((size_t)t * nheads + hh) * HD_;
    float x0 = base[d];
    float x1 = base[d + 32];
    base[d]      = f2tf32f(x0 * c - x1 * sn);
    base[d + 32] = f2tf32f(x1 * c + x0 * sn);
}

// ---------------------------------------------------------------------------
// tf32 flash attention v2: 256 threads, 2 q-heads per CTA (shared KV),
// cp.async double-buffered K/V staging (inputs pre-rounded to tf32).
// Layouts: Q,K,P at stride 68 (banks 4g+tg, conflict-free), V at stride 72
// (banks 8tg+g, conflict-free). K buffer reused as head-0's P after scores.
// grid = (S/64, HQ/2, B).
// ---------------------------------------------------------------------------
#define KSTR 68
#define VSTR 72
#define OFF_KB0 0
#define OFF_KB1 (64 * KSTR)
#define OFF_PB  (2 * 64 * KSTR)
#define OFF_VB0 (3 * 64 * KSTR)
#define OFF_VB1 (3 * 64 * KSTR + 64 * VSTR)
#define ATT_SMEM ((3 * 64 * KSTR + 2 * 64 * VSTR) * 4)

__global__ __launch_bounds__(256, 2)
void attn_mma2(const float* __restrict__ Q, const float* __restrict__ K,
               const float* __restrict__ V, float* __restrict__ O)
{
    extern __shared__ float sm[];
    const unsigned smb = (unsigned)__cvta_generic_to_shared(sm);

    const int qb   = blockIdx.x;
    const int hp   = blockIdx.y;           // head pair
    const int b    = blockIdx.z;
    const int kvh  = hp >> 1;
    const int tid  = threadIdx.x;
    const int wid  = tid >> 5;
    const int lane = tid & 31;
    const int g    = lane >> 2;
    const int tg   = lane & 3;
    const int hsel = wid >> 2;             // 0/1
    const int head = 2 * hp + hsel;
    const int qrow0 = (wid & 3) * 16;

    const float scale = 0.125f;

    // ---- Prologue: cp.async Q (both heads, natural [q][d]) + K0/V0 ----
    {
        const int hs2 = tid >> 7;          // which head this thread stages
        const int tt  = tid & 127;
        const int qhead = 2 * hp + hs2;
        const unsigned qdst = smb + (hs2 ? OFF_PB : OFF_KB1) * 4;
        #pragma unroll
        for (int j = 0; j < 8; j++) {
            int idx = tt + j * 128;        // 0..1023
            int r = idx >> 4, c = idx & 15;
            const float* src = Q + (size_t)(b * S_ + qb * 64 + r) * HID_ + qhead * HD_ + c * 4;
            CPA16(qdst + (r * KSTR + c * 4) * 4, src);
        }
        // K0 / V0
        #pragma unroll
        for (int j = 0; j < 4; j++) {
            int idx = tid + j * 256;       // 0..1023
            int r = idx >> 4, c = idx & 15;
            size_t gb = ((size_t)(b * S_ + r) * HKV_ + kvh) * HD_ + c * 4;
            CPA16(smb + (OFF_KB0 + r * KSTR + c * 4) * 4, K + gb);
            CPA16(smb + (OFF_VB0 + r * VSTR + c * 4) * 4, V + gb);
        }
        CPA_COMMIT();
        CPA_WAIT0();
    }
    __syncthreads();

    // Q fragments (already tf32-rounded bits)
    unsigned qfr[8][4];
    {
        const float* qsrc = sm + (hsel ? OFF_PB : OFF_KB1);
        #pragma unroll
        for (int kc = 0; kc < 8; kc++) {
            qfr[kc][0] = __float_as_uint(qsrc[(qrow0 + g    ) * KSTR + kc * 8 + tg    ]);
            qfr[kc][1] = __float_as_uint(qsrc[(qrow0 + g + 8) * KSTR + kc * 8 + tg    ]);
            qfr[kc][2] = __float_as_uint(qsrc[(qrow0 + g    ) * KSTR + kc * 8 + tg + 4]);
            qfr[kc][3] = __float_as_uint(qsrc[(qrow0 + g + 8) * KSTR + kc * 8 + tg + 4]);
        }
    }
    __syncthreads();   // qfr extracted before any buffer reuse

    float oacc[8][4];
    #pragma unroll
    for (int nt = 0; nt < 8; nt++)
        #pragma unroll
        for (int c = 0; c < 4; c++) oacc[nt][c] = 0.f;
    float m0 = -1e30f, m1 = -1e30f, l0 = 0.f, l1 = 0.f;

    const int qg0 = qb * 64 + qrow0 + g;
    const int qg1 = qg0 + 8;

    for (int kb = 0; kb <= qb; kb++) {
        const int s = kb & 1;
        const float* Kc = sm + (s ? OFF_KB1 : OFF_KB0);
        const float* Vc = sm + (s ? OFF_VB1 : OFF_VB0);

        if (kb < qb) {
            // stage kb+1 into other buffers
            const int so = s ^ 1;
            #pragma unroll
            for (int j = 0; j < 4; j++) {
                int idx = tid + j * 256;
                int r = idx >> 4, c = idx & 15;
                size_t gb = ((size_t)(b * S_ + (kb + 1) * 64 + r) * HKV_ + kvh) * HD_ + c * 4;
                CPA16(smb + ((so ? OFF_KB1 : OFF_KB0) + r * KSTR + c * 4) * 4, K + gb);
                CPA16(smb + ((so ? OFF_VB1 : OFF_VB0) + r * VSTR + c * 4) * 4, V + gb);
            }
            CPA_COMMIT();
            CPA_WAIT1();   // current tile's group done
        } else {
            CPA_WAIT0();
        }
        __syncthreads();

        // Scores: S = Q @ K^T  (B-frag: Kc[key][d])
        float sc[8][4];
        #pragma unroll
        for (int nt = 0; nt < 8; nt++) {
            sc[nt][0] = sc[nt][1] = sc[nt][2] = sc[nt][3] = 0.f;
            #pragma unroll
            for (int kc = 0; kc < 8; kc++) {
                unsigned b0 = __float_as_uint(Kc[(nt * 8 + g) * KSTR + kc * 8 + tg    ]);
                unsigned b1 = __float_as_uint(Kc[(nt * 8 + g) * KSTR + kc * 8 + tg + 4]);
                MMA_TF32(sc[nt], qfr[kc], b0, b1);
            }
        }

        // Scale + causal mask
        const int kbase = kb * 64;
        #pragma unroll
        for (int nt = 0; nt < 8; nt++) {
            int key0 = kbase + nt * 8 + 2 * tg;
            sc[nt][0] = (key0     > qg0) ? -1e30f : sc[nt][0] * scale;
            sc[nt][1] = (key0 + 1 > qg0) ? -1e30f : sc[nt][1] * scale;
            sc[nt][2] = (key0     > qg1) ? -1e30f : sc[nt][2] * scale;
            sc[nt][3] = (key0 + 1 > qg1) ? -1e30f : sc[nt][3] * scale;
        }

        // Row max
        float mx0 = -1e30f, mx1 = -1e30f;
        #pragma unroll
        for (int nt = 0; nt < 8; nt++) {
            mx0 = fmaxf(mx0, fmaxf(sc[nt][0], sc[nt][1]));
            mx1 = fmaxf(mx1, fmaxf(sc[nt][2], sc[nt][3]));
        }
        mx0 = fmaxf(mx0, __shfl_xor_sync(0xffffffffu, mx0, 1));
        mx0 = fmaxf(mx0, __shfl_xor_sync(0xffffffffu, mx0, 2));
        mx1 = fmaxf(mx1, __shfl_xor_sync(0xffffffffu, mx1, 1));
        mx1 = fmaxf(mx1, __shfl_xor_sync(0xffffffffu, mx1, 2));

        float mn0 = fmaxf(m0, mx0), mn1 = fmaxf(m1, mx1);
        float cr0 = __expf(m0 - mn0), cr1 = __expf(m1 - mn1);
        l0 *= cr0; l1 *= cr1;
        #pragma unroll
        for (int nt = 0; nt < 8; nt++) {
            oacc[nt][0] *= cr0; oacc[nt][1] *= cr0;
            oacc[nt][2] *= cr1; oacc[nt][3] *= cr1;
        }
        m0 = mn0; m1 = mn1;

        __syncthreads();   // both heads done reading Kc

        // P = exp(S - m) -> P buffer [q][key] stride KSTR
        float* Pb = (float*)(hsel ? (sm + OFF_PB) : Kc);
        #pragma unroll
        for (int nt = 0; nt < 8; nt++) {
            float p00 = __expf(sc[nt][0] - m0);
            float p01 = __expf(sc[nt][1] - m0);
            float p10 = __expf(sc[nt][2] - m1);
            float p11 = __expf(sc[nt][3] - m1);
            l0 += p00 + p01;
            l1 += p10 + p11;
            int kcol = nt * 8 + 2 * tg;
            *(float2*)&Pb[(qrow0 + g    ) * KSTR + kcol] =
                make_float2(f2tf32f(p00), f2tf32f(p01));
            *(float2*)&Pb[(qrow0 + g + 8) * KSTR + kcol] =
                make_float2(f2tf32f(p10), f2tf32f(p11));
        }
        __syncwarp();

        // O += P @ V
        #pragma unroll
        for (int kc = 0; kc < 8; kc++) {
            unsigned afr[4];
            afr[0] = __float_as_uint(Pb[(qrow0 + g    ) * KSTR + kc * 8 + tg    ]);
            afr[1] = __float_as_uint(Pb[(qrow0 + g + 8) * KSTR + kc * 8 + tg    ]);
            afr[2] = __float_as_uint(Pb[(qrow0 + g    ) * KSTR + kc * 8 + tg + 4]);
            afr[3] = __float_as_uint(Pb[(qrow0 + g + 8) * KSTR + kc * 8 + tg + 4]);
            #pragma unroll
            for (int nt = 0; nt < 8; nt++) {
                unsigned b0 = __float_as_uint(Vc[(kc * 8 + tg    ) * VSTR + nt * 8 + g]);
                unsigned b1 = __float_as_uint(Vc[(kc * 8 + tg + 4) * VSTR + nt * 8 + g]);
                MMA_TF32(oacc[nt], afr, b0, b1);
            }
        }
        __syncthreads();   // Vc/Pb(=Kc) free before next restage
    }

    // Final normalize + write
    l0 += __shfl_xor_sync(0xffffffffu, l0, 1);
    l0 += __shfl_xor_sync(0xffffffffu, l0, 2);
    l1 += __shfl_xor_sync(0xffffffffu, l1, 1);
    l1 += __shfl_xor_sync(0xffffffffu, l1, 2);
    float inv0 = 1.f / l0, inv1 = 1.f / l1;

    const size_t tok0 = (size_t)(b * S_ + qb * 64 + qrow0 + g);
    const size_t tok1 = tok0 + 8;
    #pragma unroll
    for (int nt = 0; nt < 8; nt++) {
        int col = head * HD_ + nt * 8 + 2 * tg;
        *(float2*)(O + tok0 * HID_ + col) =
            make_float2(oacc[nt][0] * inv0, oacc[nt][1] * inv0);
        *(float2*)(O + tok1 * HID_ + col) =
            make_float2(oacc[nt][2] * inv1, oacc[nt][3] * inv1);
    }
}

// ---------------------------------------------------------------------------
// Launch
// ---------------------------------------------------------------------------
extern "C" void kernel_launch(void* const* d_in, const int* in_sizes, int n_in,
                              void* d_out, int out_size)
{
    const float* hid  = (const float*)d_in[0];
    const float* cosT = (const float*)d_in[1];
    const float* sinT = (const float*)d_in[2];
    const float* Wq   = (const float*)d_in[3];
    const float* Wk   = (const float*)d_in[4];
    const float* Wv   = (const float*)d_in[5];
    const float* Wo   = (const float*)d_in[6];
    float* out = (float*)d_out;

    float *q_p, *k_p, *v_p, *attn_p;
    cudaGetSymbolAddress((void**)&q_p,    g_q);
    cudaGetSymbolAddress((void**)&k_p,    g_k);
    cudaGetSymbolAddress((void**)&v_p,    g_v);
    cudaGetSymbolAddress((void**)&attn_p, g_attn);

    static bool attr_done = false;
    if (!attr_done) {
        cudaFuncSetAttribute(attn_mma2,
                             cudaFuncAttributeMaxDynamicSharedMemorySize, ATT_SMEM);
        attr_done = true;
    }

    // Fused QKV projection (V output tf32-rounded)
    {
        dim3 g(24, 16);
        mma_gemm_qkv<<<g, 256>>>(hid, Wq, Wk, Wv, q_p, k_p, v_p);
    }

    // RoPE (outputs tf32-rounded)
    {
        int totq = MTOK * HQ_ * 32;
        rope_kernel<<<(totq + 255) / 256, 256>>>(q_p, cosT, sinT, HQ_);
        int totk = MTOK * HKV_ * 32;
        rope_kernel<<<(totk + 255) / 256, 256>>>(k_p, cosT, sinT, HKV_);
    }

    // Attention
    {
        dim3 ga(S_ / 64, HQ_ / 2, B_);
        attn_mma2<<<ga, 256, ATT_SMEM>>>(q_p, k_p, v_p, attn_p);
    }

    // Output projection
    {
        dim3 go(16, 16);
        mma_gemm_qkv<<<go, 256>>>(attn_p, Wo, Wo, Wo, out, out, out);
    }
}

// round 10
// speedup vs baseline: 1.4024x; 1.4024x over previous
#include <cuda_runtime.h>
#include <cuda_bf16.h>
#include <math.h>

// Problem constants
#define B_    2
#define S_    1024
#define HID_  2048
#define HQ_   32
#define HKV_  8
#define HD_   64
#define MTOK  (B_ * S_)
#define NREP  (HQ_ / HKV_)

// Scratch
__device__ float g_q[MTOK * HID_];
__device__ float g_k[MTOK * HKV_ * HD_];
__device__ float g_v[MTOK * HKV_ * HD_];
__device__ float g_attn[MTOK * HID_];
// tf32-rounded operand copies
__device__ float g_rh[MTOK * HID_];
__device__ float g_wq[HID_ * HID_];
__device__ float g_wk[HID_ * 512];
__device__ float g_wv[HID_ * 512];
__device__ float g_wo[HID_ * HID_];

__device__ __forceinline__ unsigned f2tf32(float x) {
    unsigned r;
    asm("cvt.rna.tf32.f32 %0, %1;" : "=r"(r) : "f"(x));
    return r;
}
__device__ __forceinline__ float f2tf32f(float x) {
    return __uint_as_float(f2tf32(x));
}

#define MMA_TF32(D, A, B0, B1)                                              \
    asm volatile(                                                           \
        "mma.sync.aligned.m16n8k8.row.col.f32.tf32.tf32.f32 "               \
        "{%0,%1,%2,%3}, {%4,%5,%6,%7}, {%8,%9}, {%0,%1,%2,%3};"             \
        : "+f"((D)[0]), "+f"((D)[1]), "+f"((D)[2]), "+f"((D)[3])            \
        : "r"((A)[0]), "r"((A)[1]), "r"((A)[2]), "r"((A)[3]),               \
          "r"(B0), "r"(B1))

#define CPA16(smu32, gptr) \
    asm volatile("cp.async.cg.shared.global [%0], [%1], 16;" :: "r"(smu32), "l"(gptr))
#define CPA_COMMIT() asm volatile("cp.async.commit_group;")
#define CPA_WAIT0()  asm volatile("cp.async.wait_group 0;" ::: "memory")
#define CPA_WAIT1()  asm volatile("cp.async.wait_group 1;" ::: "memory")

// ---------------------------------------------------------------------------
// tf32 rounding pre-pass (float4 elementwise)
// ---------------------------------------------------------------------------
__global__ void round_tf32_kernel(const float* __restrict__ src,
                                  float* __restrict__ dst, int n4)
{
    int i = blockIdx.x * blockDim.x + threadIdx.x;
    if (i >= n4) return;
    float4 v = ((const float4*)src)[i];
    float4 r;
    r.x = f2tf32f(v.x); r.y = f2tf32f(v.y);
    r.z = f2tf32f(v.z); r.w = f2tf32f(v.w);
    ((float4*)dst)[i] = r;
}

// ---------------------------------------------------------------------------
// Pipelined tf32 GEMM. Inputs MUST be pre-rounded to tf32 bit patterns.
// C[M,N] = A[M,K=2048] @ B[K,N]. 128x128x32 tile, 256 thr, 3-stage cp.async.
// As: [128][36] (row-major, conflict-free A-frags), Bs: [32][136].
// Fused QKV via blockIdx.x split; V output rounded for attention reuse.
// ---------------------------------------------------------------------------
#define GSTG  3
#define ASTR  36
#define BSTR  136
#define AS_SZ (128 * ASTR)
#define BS_SZ (32 * BSTR)
#define STG_SZ (AS_SZ + BS_SZ)
#define GEMM_SMEM (GSTG * STG_SZ * 4)
#define NKT   (HID_ / 32)

__global__ __launch_bounds__(256, 2)
void mma_gemm_pipe(const float* __restrict__ A,
                   const float* __restrict__ Wq, const float* __restrict__ Wk,
                   const float* __restrict__ Wv,
                   float* __restrict__ Cq, float* __restrict__ Ck,
                   float* __restrict__ Cv)
{
    extern __shared__ float smg[];
    const unsigned smb = (unsigned)__cvta_generic_to_shared(smg);

    const int bx = blockIdx.x;
    const int by = blockIdx.y;

    const float* Bp; float* Cp; int Nb, n0; bool cvtV = false;
    if (bx < 16)      { Bp = Wq; Cp = Cq; Nb = 2048; n0 = bx * 128; }
    else if (bx < 20) { Bp = Wk; Cp = Ck; Nb = 512;  n0 = (bx - 16) * 128; }
    else              { Bp = Wv; Cp = Cv; Nb = 512;  n0 = (bx - 20) * 128; cvtV = true; }

    const int tid  = threadIdx.x;
    const int wid  = tid >> 5;
    const int lane = tid & 31;
    const int wm   = wid >> 2;
    const int wn   = wid & 3;
    const int g    = lane >> 2;
    const int tg   = lane & 3;
    const int m0   = by * 128;

    const int arow = tid >> 1;            // 0..127
    const int acol = (tid & 1) * 16;      // 0/16
    const int bkr  = tid >> 3;            // 0..31
    const int bcol = (tid & 7) * 16;      // 0..112

    float acc[4][4][4];
    #pragma unroll
    for (int mi = 0; mi < 4; mi++)
        #pragma unroll
        for (int ni = 0; ni < 4; ni++)
            #pragma unroll
            for (int c = 0; c < 4; c++) acc[mi][ni][c] = 0.f;

    // tile loader
    auto load_tile = [&](int kt, int stg) {
        const float* As_g = A + (size_t)(m0 + arow) * HID_ + kt * 32 + acol;
        unsigned as = smb + (stg * STG_SZ + arow * ASTR + acol) * 4;
        #pragma unroll
        for (int j = 0; j < 4; j++)
            CPA16(as + j * 16, As_g + j * 4);
        const float* Bs_g = Bp + (size_t)(kt * 32 + bkr) * Nb + n0 + bcol;
        unsigned bs = smb + (stg * STG_SZ + AS_SZ + bkr * BSTR + bcol) * 4;
        #pragma unroll
        for (int j = 0; j < 4; j++)
            CPA16(bs + j * 16, Bs_g + j * 4);
        CPA_COMMIT();
    };

    load_tile(0, 0);
    load_tile(1, 1);

    for (int kt = 0; kt < NKT; kt++) {
        if (kt < NKT - 1) { CPA_WAIT1(); } else { CPA_WAIT0(); }
        __syncthreads();

        const float* As_ = smg + (kt % GSTG) * STG_SZ;
        const float* Bs_ = As_ + AS_SZ;

        #pragma unroll
        for (int ks = 0; ks < 4; ks++) {
            unsigned afr[4][4], bfr[4][2];
            #pragma unroll
            for (int mi = 0; mi < 4; mi++) {
                int mb = wm * 64 + mi * 16;
                afr[mi][0] = __float_as_uint(As_[(mb + g    ) * ASTR + ks * 8 + tg    ]);
                afr[mi][1] = __float_as_uint(As_[(mb + g + 8) * ASTR + ks * 8 + tg    ]);
                afr[mi][2] = __float_as_uint(As_[(mb + g    ) * ASTR + ks * 8 + tg + 4]);
                afr[mi][3] = __float_as_uint(As_[(mb + g + 8) * ASTR + ks * 8 + tg + 4]);
            }
            #pragma unroll
            for (int ni = 0; ni < 4; ni++) {
                int nb = wn * 32 + ni * 8;
                bfr[ni][0] = __float_as_uint(Bs_[(ks * 8 + tg    ) * BSTR + nb + g]);
                bfr[ni][1] = __float_as_uint(Bs_[(ks * 8 + tg + 4) * BSTR + nb + g]);
            }
            #pragma unroll
            for (int mi = 0; mi < 4; mi++)
                #pragma unroll
                for (int ni = 0; ni < 4; ni++)
                    MMA_TF32(acc[mi][ni], afr[mi], bfr[ni][0], bfr[ni][1]);
        }
        __syncthreads();

        if (kt + 2 < NKT) load_tile(kt + 2, (kt + 2) % GSTG);
    }

    #pragma unroll
    for (int mi = 0; mi < 4; mi++) {
        int row0 = m0 + wm * 64 + mi * 16 + g;
        #pragma unroll
        for (int ni = 0; ni < 4; ni++) {
            int col = n0 + wn * 32 + ni * 8 + tg * 2;
            float v0 = acc[mi][ni][0], v1 = acc[mi][ni][1];
            float v2 = acc[mi][ni][2], v3 = acc[mi][ni][3];
            if (cvtV) {
                v0 = f2tf32f(v0); v1 = f2tf32f(v1);
                v2 = f2tf32f(v2); v3 = f2tf32f(v3);
            }
            *(float2*)(Cp + (size_t)row0 * Nb + col) = make_float2(v0, v1);
            *(float2*)(Cp + (size_t)(row0 + 8) * Nb + col) = make_float2(v2, v3);
        }
    }
}

// ---------------------------------------------------------------------------
// RoPE (in place), output rounded to tf32 bit pattern.
// ---------------------------------------------------------------------------
__global__ void rope_kernel(float* __restrict__ X,
                            const float* __restrict__ cosT,
                            const float* __restrict__ sinT,
                            int nheads)
{
    int idx = blockIdx.x * blockDim.x + threadIdx.x;
    int total = MTOK * nheads * 32;
    if (idx >= total) return;
    int d  = idx & 31;
    int hh = (idx >> 5) % nheads;
    int t  = idx / (32 * nheads);
    int s  = t & (S_ - 1);

    float c  = __ldg(cosT + s * HD_ + d);
    float sn = __ldg(sinT + s * HD_ + d);

    float* base = X + ((size_t)t * nheads + hh) * HD_;
    float x0 = base[d];
    float x1 = base[d + 32];
    base[d]      = f2tf32f(x0 * c - x1 * sn);
    base[d + 32] = f2tf32f(x1 * c + x0 * sn);
}

// ---------------------------------------------------------------------------
// tf32 flash attention: 256 threads, 2 q-heads per CTA (shared KV),
// cp.async double-buffered K/V staging. Output rounded to tf32 (feeds O GEMM).
// ---------------------------------------------------------------------------
#define KSTR 68
#define VSTR 72
#define OFF_KB0 0
#define OFF_KB1 (64 * KSTR)
#define OFF_PB  (2 * 64 * KSTR)
#define OFF_VB0 (3 * 64 * KSTR)
#define OFF_VB1 (3 * 64 * KSTR + 64 * VSTR)
#define ATT_SMEM ((3 * 64 * KSTR + 2 * 64 * VSTR) * 4)

__global__ __launch_bounds__(256, 2)
void attn_mma2(const float* __restrict__ Q, const float* __restrict__ K,
               const float* __restrict__ V, float* __restrict__ O)
{
    extern __shared__ float sm[];
    const unsigned smb = (unsigned)__cvta_generic_to_shared(sm);

    const int qb   = blockIdx.x;
    const int hp   = blockIdx.y;
    const int b    = blockIdx.z;
    const int kvh  = hp >> 1;
    const int tid  = threadIdx.x;
    const int wid  = tid >> 5;
    const int lane = tid & 31;
    const int g    = lane >> 2;
    const int tg   = lane & 3;
    const int hsel = wid >> 2;
    const int head = 2 * hp + hsel;
    const int qrow0 = (wid & 3) * 16;

    const float scale = 0.125f;

    // ---- Prologue: cp.async Q (both heads) + K0/V0 ----
    {
        const int hs2 = tid >> 7;
        const int tt  = tid & 127;
        const int qhead = 2 * hp + hs2;
        const unsigned qdst = smb + (hs2 ? OFF_PB : OFF_KB1) * 4;
        #pragma unroll
        for (int j = 0; j < 8; j++) {
            int idx = tt + j * 128;
            int r = idx >> 4, c = idx & 15;
            const float* src = Q + (size_t)(b * S_ + qb * 64 + r) * HID_ + qhead * HD_ + c * 4;
            CPA16(qdst + (r * KSTR + c * 4) * 4, src);
        }
        #pragma unroll
        for (int j = 0; j < 4; j++) {
            int idx = tid + j * 256;
            int r = idx >> 4, c = idx & 15;
            size_t gb = ((size_t)(b * S_ + r) * HKV_ + kvh) * HD_ + c * 4;
            CPA16(smb + (OFF_KB0 + r * KSTR + c * 4) * 4, K + gb);
            CPA16(smb + (OFF_VB0 + r * VSTR + c * 4) * 4, V + gb);
        }
        CPA_COMMIT();
        CPA_WAIT0();
    }
    __syncthreads();

    unsigned qfr[8][4];
    {
        const float* qsrc = sm + (hsel ? OFF_PB : OFF_KB1);
        #pragma unroll
        for (int kc = 0; kc < 8; kc++) {
            qfr[kc][0] = __float_as_uint(qsrc[(qrow0 + g    ) * KSTR + kc * 8 + tg    ]);
            qfr[kc][1] = __float_as_uint(qsrc[(qrow0 + g + 8) * KSTR + kc * 8 + tg    ]);
            qfr[kc][2] = __float_as_uint(qsrc[(qrow0 + g    ) * KSTR + kc * 8 + tg + 4]);
            qfr[kc][3] = __float_as_uint(qsrc[(qrow0 + g + 8) * KSTR + kc * 8 + tg + 4]);
        }
    }
    __syncthreads();

    float oacc[8][4];
    #pragma unroll
    for (int nt = 0; nt < 8; nt++)
        #pragma unroll
        for (int c = 0; c < 4; c++) oacc[nt][c] = 0.f;
    float m0 = -1e30f, m1 = -1e30f, l0 = 0.f, l1 = 0.f;

    const int qg0 = qb * 64 + qrow0 + g;
    const int qg1 = qg0 + 8;

    for (int kb = 0; kb <= qb; kb++) {
        const int s = kb & 1;
        const float* Kc = sm + (s ? OFF_KB1 : OFF_KB0);
        const float* Vc = sm + (s ? OFF_VB1 : OFF_VB0);

        if (kb < qb) {
            const int so = s ^ 1;
            #pragma unroll
            for (int j = 0; j < 4; j++) {
                int idx = tid + j * 256;
                int r = idx >> 4, c = idx & 15;
                size_t gb = ((size_t)(b * S_ + (kb + 1) * 64 + r) * HKV_ + kvh) * HD_ + c * 4;
                CPA16(smb + ((so ? OFF_KB1 : OFF_KB0) + r * KSTR + c * 4) * 4, K + gb);
                CPA16(smb + ((so ? OFF_VB1 : OFF_VB0) + r * VSTR + c * 4) * 4, V + gb);
            }
            CPA_COMMIT();
            CPA_WAIT1();
        } else {
            CPA_WAIT0();
        }
        __syncthreads();

        float sc[8][4];
        #pragma unroll
        for (int nt = 0; nt < 8; nt++) {
            sc[nt][0] = sc[nt][1] = sc[nt][2] = sc[nt][3] = 0.f;
            #pragma unroll
            for (int kc = 0; kc < 8; kc++) {
                unsigned b0 = __float_as_uint(Kc[(nt * 8 + g) * KSTR + kc * 8 + tg    ]);
                unsigned b1 = __float_as_uint(Kc[(nt * 8 + g) * KSTR + kc * 8 + tg + 4]);
                MMA_TF32(sc[nt], qfr[kc], b0, b1);
            }
        }

        const int kbase = kb * 64;
        #pragma unroll
        for (int nt = 0; nt < 8; nt++) {
            int key0 = kbase + nt * 8 + 2 * tg;
            sc[nt][0] = (key0     > qg0) ? -1e30f : sc[nt][0] * scale;
            sc[nt][1] = (key0 + 1 > qg0) ? -1e30f : sc[nt][1] * scale;
            sc[nt][2] = (key0     > qg1) ? -1e30f : sc[nt][2] * scale;
            sc[nt][3] = (key0 + 1 > qg1) ? -1e30f : sc[nt][3] * scale;
        }

        float mx0 = -1e30f, mx1 = -1e30f;
        #pragma unroll
        for (int nt = 0; nt < 8; nt++) {
            mx0 = fmaxf(mx0, fmaxf(sc[nt][0], sc[nt][1]));
            mx1 = fmaxf(mx1, fmaxf(sc[nt][2], sc[nt][3]));
        }
        mx0 = fmaxf(mx0, __shfl_xor_sync(0xffffffffu, mx0, 1));
        mx0 = fmaxf(mx0, __shfl_xor_sync(0xffffffffu, mx0, 2));
        mx1 = fmaxf(mx1, __shfl_xor_sync(0xffffffffu, mx1, 1));
        mx1 = fmaxf(mx1, __shfl_xor_sync(0xffffffffu, mx1, 2));

        float mn0 = fmaxf(m0, mx0), mn1 = fmaxf(m1, mx1);
        float cr0 = __expf(m0 - mn0), cr1 = __expf(m1 - mn1);
        l0 *= cr0; l1 *= cr1;
        #pragma unroll
        for (int nt = 0; nt < 8; nt++) {
            oacc[nt][0] *= cr0; oacc[nt][1] *= cr0;
            oacc[nt][2] *= cr1; oacc[nt][3] *= cr1;
        }
        m0 = mn0; m1 = mn1;

        __syncthreads();

        float* Pb = (float*)(hsel ? (sm + OFF_PB) : Kc);
        #pragma unroll
        for (int nt = 0; nt < 8; nt++) {
            float p00 = __expf(sc[nt][0] - m0);
            float p01 = __expf(sc[nt][1] - m0);
            float p10 = __expf(sc[nt][2] - m1);
            float p11 = __expf(sc[nt][3] - m1);
            l0 += p00 + p01;
            l1 += p10 + p11;
            int kcol = nt * 8 + 2 * tg;
            *(float2*)&Pb[(qrow0 + g    ) * KSTR + kcol] =
                make_float2(f2tf32f(p00), f2tf32f(p01));
            *(float2*)&Pb[(qrow0 + g + 8) * KSTR + kcol] =
                make_float2(f2tf32f(p10), f2tf32f(p11));
        }
        __syncwarp();

        #pragma unroll
        for (int kc = 0; kc < 8; kc++) {
            unsigned afr[4];
            afr[0] = __float_as_uint(Pb[(qrow0 + g    ) * KSTR + kc * 8 + tg    ]);
            afr[1] = __float_as_uint(Pb[(qrow0 + g + 8) * KSTR + kc * 8 + tg    ]);
            afr[2] = __float_as_uint(Pb[(qrow0 + g    ) * KSTR + kc * 8 + tg + 4]);
            afr[3] = __float_as_uint(Pb[(qrow0 + g + 8) * KSTR + kc * 8 + tg + 4]);
            #pragma unroll
            for (int nt = 0; nt < 8; nt++) {
                unsigned b0 = __float_as_uint(Vc[(kc * 8 + tg    ) * VSTR + nt * 8 + g]);
                unsigned b1 = __float_as_uint(Vc[(kc * 8 + tg + 4) * VSTR + nt * 8 + g]);
                MMA_TF32(oacc[nt], afr, b0, b1);
            }
        }
        __syncthreads();
    }

    l0 += __shfl_xor_sync(0xffffffffu, l0, 1);
    l0 += __shfl_xor_sync(0xffffffffu, l0, 2);
    l1 += __shfl_xor_sync(0xffffffffu, l1, 1);
    l1 += __shfl_xor_sync(0xffffffffu, l1, 2);
    float inv0 = 1.f / l0, inv1 = 1.f / l1;

    const size_t tok0 = (size_t)(b * S_ + qb * 64 + qrow0 + g);
    const size_t tok1 = tok0 + 8;
    #pragma unroll
    for (int nt = 0; nt < 8; nt++) {
        int col = head * HD_ + nt * 8 + 2 * tg;
        *(float2*)(O + tok0 * HID_ + col) =
            make_float2(f2tf32f(oacc[nt][0] * inv0), f2tf32f(oacc[nt][1] * inv0));
        *(float2*)(O + tok1 * HID_ + col) =
            make_float2(f2tf32f(oacc[nt][2] * inv1), f2tf32f(oacc[nt][3] * inv1));
    }
}

// ---------------------------------------------------------------------------
// Launch
// ---------------------------------------------------------------------------
extern "C" void kernel_launch(void* const* d_in, const int* in_sizes, int n_in,
                              void* d_out, int out_size)
{
    const float* hid  = (const float*)d_in[0];
    const float* cosT = (const float*)d_in[1];
    const float* sinT = (const float*)d_in[2];
    const float* Wq   = (const float*)d_in[3];
    const float* Wk   = (const float*)d_in[4];
    const float* Wv   = (const float*)d_in[5];
    const float* Wo   = (const float*)d_in[6];
    float* out = (float*)d_out;

    float *q_p, *k_p, *v_p, *attn_p, *rh_p, *wq_p, *wk_p, *wv_p, *wo_p;
    cudaGetSymbolAddress((void**)&q_p,    g_q);
    cudaGetSymbolAddress((void**)&k_p,    g_k);
    cudaGetSymbolAddress((void**)&v_p,    g_v);
    cudaGetSymbolAddress((void**)&attn_p, g_attn);
    cudaGetSymbolAddress((void**)&rh_p,   g_rh);
    cudaGetSymbolAddress((void**)&wq_p,   g_wq);
    cudaGetSymbolAddress((void**)&wk_p,   g_wk);
    cudaGetSymbolAddress((void**)&wv_p,   g_wv);
    cudaGetSymbolAddress((void**)&wo_p,   g_wo);

    cudaFuncSetAttribute(attn_mma2,
                         cudaFuncAttributeMaxDynamicSharedMemorySize, ATT_SMEM);
    cudaFuncSetAttribute(mma_gemm_pipe,
                         cudaFuncAttributeMaxDynamicSharedMemorySize, GEMM_SMEM);

    // Pre-round operands to tf32
    {
        int n4h = MTOK * HID_ / 4;
        round_tf32_kernel<<<(n4h + 255) / 256, 256>>>(hid, rh_p, n4h);
        int n4q = HID_ * HID_ / 4;
        round_tf32_kernel<<<(n4q + 255) / 256, 256>>>(Wq, wq_p, n4q);
        int n4k = HID_ * 512 / 4;
        round_tf32_kernel<<<(n4k + 255) / 256, 256>>>(Wk, wk_p, n4k);
        round_tf32_kernel<<<(n4k + 255) / 256, 256>>>(Wv, wv_p, n4k);
        round_tf32_kernel<<<(n4q + 255) / 256, 256>>>(Wo, wo_p, n4q);
    }

    // Fused QKV projection
    {
        dim3 g(24, 16);
        mma_gemm_pipe<<<g, 256, GEMM_SMEM>>>(rh_p, wq_p, wk_p, wv_p, q_p, k_p, v_p);
    }

    // RoPE (outputs tf32-rounded)
    {
        int totq = MTOK * HQ_ * 32;
        rope_kernel<<<(totq + 255) / 256, 256>>>(q_p, cosT, sinT, HQ_);
        int totk = MTOK * HKV_ * 32;
        rope_kernel<<<(totk + 255) / 256, 256>>>(k_p, cosT, sinT, HKV_);
    }

    // Attention
    {
        dim3 ga(S_ / 64, HQ_ / 2, B_);
        attn_mma2<<<ga, 256, ATT_SMEM>>>(q_p, k_p, v_p, attn_p);
    }

    // Output projection
    {
        dim3 go(16, 16);
        mma_gemm_pipe<<<go, 256, GEMM_SMEM>>>(attn_p, wo_p, wo_p, wo_p, out, out, out);
    }
}

// round 14
// speedup vs baseline: 1.6712x; 1.1917x over previous
#include <cuda_runtime.h>
#include <cuda_bf16.h>
#include <math.h>

// Problem constants
#define B_    2
#define S_    1024
#define HID_  2048
#define HQ_   32
#define HKV_  8
#define HD_   64
#define MTOK  (B_ * S_)
#define NREP  (HQ_ / HKV_)

// Scratch
__device__ float g_q[MTOK * HID_];
__device__ float g_k[MTOK * HKV_ * HD_];
__device__ float g_v[MTOK * HKV_ * HD_];
__device__ float g_attn[MTOK * HID_];
// tf32-rounded operand copies
__device__ float g_rh[MTOK * HID_];
__device__ float g_wq[HID_ * HID_];
__device__ float g_wk[HID_ * 512];
__device__ float g_wv[HID_ * 512];
__device__ float g_wo[HID_ * HID_];

__device__ __forceinline__ unsigned f2tf32(float x) {
    unsigned r;
    asm("cvt.rna.tf32.f32 %0, %1;" : "=r"(r) : "f"(x));
    return r;
}
__device__ __forceinline__ float f2tf32f(float x) {
    return __uint_as_float(f2tf32(x));
}

#define MMA_TF32(D, A, B0, B1)                                              \
    asm volatile(                                                           \
        "mma.sync.aligned.m16n8k8.row.col.f32.tf32.tf32.f32 "               \
        "{%0,%1,%2,%3}, {%4,%5,%6,%7}, {%8,%9}, {%0,%1,%2,%3};"             \
        : "+f"((D)[0]), "+f"((D)[1]), "+f"((D)[2]), "+f"((D)[3])            \
        : "r"((A)[0]), "r"((A)[1]), "r"((A)[2]), "r"((A)[3]),               \
          "r"(B0), "r"(B1))

#define CPA16(smu32, gptr) \
    asm volatile("cp.async.cg.shared.global [%0], [%1], 16;" :: "r"(smu32), "l"(gptr))
#define CPA_COMMIT() asm volatile("cp.async.commit_group;")
#define CPA_WAIT0()  asm volatile("cp.async.wait_group 0;" ::: "memory")
#define CPA_WAIT1()  asm volatile("cp.async.wait_group 1;" ::: "memory")

// ---------------------------------------------------------------------------
// Merged tf32 rounding pre-pass: one launch, 5 segments (f4 units).
// ---------------------------------------------------------------------------
#define SEG0 (MTOK * HID_ / 4)
#define SEG1 (SEG0 + HID_ * HID_ / 4)
#define SEG2 (SEG1 + HID_ * 512 / 4)
#define SEG3 (SEG2 + HID_ * 512 / 4)
#define SEG4 (SEG3 + HID_ * HID_ / 4)

__global__ void round_all_kernel(const float* __restrict__ hid,
                                 const float* __restrict__ Wq,
                                 const float* __restrict__ Wk,
                                 const float* __restrict__ Wv,
                                 const float* __restrict__ Wo,
                                 float* __restrict__ rh, float* __restrict__ wq,
                                 float* __restrict__ wk, float* __restrict__ wv,
                                 float* __restrict__ wo)
{
    int i = blockIdx.x * blockDim.x + threadIdx.x;
    if (i >= SEG4) return;
    const float4* src; float4* dst; int off;
    if (i < SEG0)      { src = (const float4*)hid; dst = (float4*)rh; off = 0; }
    else if (i < SEG1) { src = (const float4*)Wq;  dst = (float4*)wq; off = SEG0; }
    else if (i < SEG2) { src = (const float4*)Wk;  dst = (float4*)wk; off = SEG1; }
    else if (i < SEG3) { src = (const float4*)Wv;  dst = (float4*)wv; off = SEG2; }
    else               { src = (const float4*)Wo;  dst = (float4*)wo; off = SEG3; }
    int j = i - off;
    float4 v = src[j];
    float4 r;
    r.x = f2tf32f(v.x); r.y = f2tf32f(v.y);
    r.z = f2tf32f(v.z); r.w = f2tf32f(v.w);
    dst[j] = r;
}

// ---------------------------------------------------------------------------
// Pipelined tf32 GEMM v2. Inputs pre-rounded to tf32 bit patterns.
// CTA 128x128x32, 128 threads (4 warps, 2x2), warp tile 64x64.
// 3-stage cp.async. As [128][36], Bs [32][136] (conflict-free frag LDS).
// ---------------------------------------------------------------------------
#define GSTG  3
#define ASTR  36
#define BSTR  136
#define AS_SZ (128 * ASTR)
#define BS_SZ (32 * BSTR)
#define STG_SZ (AS_SZ + BS_SZ)
#define GEMM_SMEM (GSTG * STG_SZ * 4)
#define NKT   (HID_ / 32)

__global__ __launch_bounds__(128, 2)
void mma_gemm_pipe(const float* __restrict__ A,
                   const float* __restrict__ Wq, const float* __restrict__ Wk,
                   const float* __restrict__ Wv,
                   float* __restrict__ Cq, float* __restrict__ Ck,
                   float* __restrict__ Cv)
{
    extern __shared__ float smg[];
    const unsigned smb = (unsigned)__cvta_generic_to_shared(smg);

    const int bx = blockIdx.x;
    const int by = blockIdx.y;

    const float* Bp; float* Cp; int Nb, n0; bool cvtV = false;
    if (bx < 16)      { Bp = Wq; Cp = Cq; Nb = 2048; n0 = bx * 128; }
    else if (bx < 20) { Bp = Wk; Cp = Ck; Nb = 512;  n0 = (bx - 16) * 128; }
    else              { Bp = Wv; Cp = Cv; Nb = 512;  n0 = (bx - 20) * 128; cvtV = true; }

    const int tid  = threadIdx.x;
    const int wid  = tid >> 5;
    const int lane = tid & 31;
    const int wm   = wid >> 1;
    const int wn   = wid & 1;
    const int g    = lane >> 2;
    const int tg   = lane & 3;
    const int m0   = by * 128;

    const int ar   = tid >> 1;
    const int ac   = (tid & 1) * 16;
    const int br   = tid >> 3;
    const int bc   = (tid & 7) * 4;

    float acc[4][8][4];
    #pragma unroll
    for (int mi = 0; mi < 4; mi++)
        #pragma unroll
        for (int ni = 0; ni < 8; ni++)
            #pragma unroll
            for (int c = 0; c < 4; c++) acc[mi][ni][c] = 0.f;

    auto load_tile = [&](int kt, int stg) {
        #pragma unroll
        for (int j = 0; j < 2; j++) {
            const float* ag = A + (size_t)(m0 + ar + j * 64) * HID_ + kt * 32 + ac;
            unsigned as = smb + (stg * STG_SZ + (ar + j * 64) * ASTR + ac) * 4;
            #pragma unroll
            for (int jj = 0; jj < 4; jj++)
                CPA16(as + jj * 16, ag + jj * 4);
        }
        #pragma unroll
        for (int j = 0; j < 2; j++) {
            const float* bg = Bp + (size_t)(kt * 32 + br + j * 16) * Nb + n0 + bc;
            unsigned bs = smb + (stg * STG_SZ + AS_SZ + (br + j * 16) * BSTR + bc) * 4;
            #pragma unroll
            for (int i = 0; i < 4; i++)
                CPA16(bs + i * 32 * 4, bg + i * 32);
        }
        CPA_COMMIT();
    };

    load_tile(0, 0);
    load_tile(1, 1);

    for (int kt = 0; kt < NKT; kt++) {
        if (kt < NKT - 1) { CPA_WAIT1(); } else { CPA_WAIT0(); }
        __syncthreads();

        const float* As_ = smg + (kt % GSTG) * STG_SZ;
        const float* Bs_ = As_ + AS_SZ;

        #pragma unroll
        for (int ks = 0; ks < 4; ks++) {
            unsigned afr[4][4], bfr[8][2];
            #pragma unroll
            for (int mi = 0; mi < 4; mi++) {
                int mb = wm * 64 + mi * 16;
                afr[mi][0] = __float_as_uint(As_[(mb + g    ) * ASTR + ks * 8 + tg    ]);
                afr[mi][1] = __float_as_uint(As_[(mb + g + 8) * ASTR + ks * 8 + tg    ]);
                afr[mi][2] = __float_as_uint(As_[(mb + g    ) * ASTR + ks * 8 + tg + 4]);
                afr[mi][3] = __float_as_uint(As_[(mb + g + 8) * ASTR + ks * 8 + tg + 4]);
            }
            #pragma unroll
            for (int ni = 0; ni < 8; ni++) {
                int nb = wn * 64 + ni * 8;
                bfr[ni][0] = __float_as_uint(Bs_[(ks * 8 + tg    ) * BSTR + nb + g]);
                bfr[ni][1] = __float_as_uint(Bs_[(ks * 8 + tg + 4) * BSTR + nb + g]);
            }
            #pragma unroll
            for (int mi = 0; mi < 4; mi++)
                #pragma unroll
                for (int ni = 0; ni < 8; ni++)
                    MMA_TF32(acc[mi][ni], afr[mi], bfr[ni][0], bfr[ni][1]);
        }
        __syncthreads();

        if (kt + 2 < NKT) load_tile(kt + 2, (kt + 2) % GSTG);
    }

    #pragma unroll
    for (int mi = 0; mi < 4; mi++) {
        int row0 = m0 + wm * 64 + mi * 16 + g;
        #pragma unroll
        for (int ni = 0; ni < 8; ni++) {
            int col = n0 + wn * 64 + ni * 8 + tg * 2;
            float v0 = acc[mi][ni][0], v1 = acc[mi][ni][1];
            float v2 = acc[mi][ni][2], v3 = acc[mi][ni][3];
            if (cvtV) {
                v0 = f2tf32f(v0); v1 = f2tf32f(v1);
                v2 = f2tf32f(v2); v3 = f2tf32f(v3);
            }
            *(float2*)(Cp + (size_t)row0 * Nb + col) = make_float2(v0, v1);
            *(float2*)(Cp + (size_t)(row0 + 8) * Nb + col) = make_float2(v2, v3);
        }
    }
}

// ---------------------------------------------------------------------------
// RoPE (in place), output rounded to tf32 bit pattern.
// ---------------------------------------------------------------------------
__global__ void rope_kernel(float* __restrict__ X,
                            const float* __restrict__ cosT,
                            const float* __restrict__ sinT,
                            int nheads)
{
    int idx = blockIdx.x * blockDim.x + threadIdx.x;
    int total = MTOK * nheads * 32;
    if (idx >= total) return;
    int d  = idx & 31;
    int hh = (idx >> 5) % nheads;
    int t  = idx / (32 * nheads);
    int s  = t & (S_ - 1);

    float c  = __ldg(cosT + s * HD_ + d);
    float sn = __ldg(sinT + s * HD_ + d);

    float* base = X + ((size_t)t * nheads + hh) * HD_;
    float x0 = base[d];
    float x1 = base[d + 32];
    base[d]      = f2tf32f(x0 * c - x1 * sn);
    base[d + 32] = f2tf32f(x1 * c + x0 * sn);
}

// ---------------------------------------------------------------------------
// tf32 flash attention: 256 threads, 2 q-heads per CTA (shared KV),
// cp.async double-buffered K/V staging. Output rounded to tf32.
// ---------------------------------------------------------------------------
#define KSTR 68
#define VSTR 72
#define OFF_KB0 0
#define OFF_KB1 (64 * KSTR)
#define OFF_PB  (2 * 64 * KSTR)
#define OFF_VB0 (3 * 64 * KSTR)
#define OFF_VB1 (3 * 64 * KSTR + 64 * VSTR)
#define ATT_SMEM ((3 * 64 * KSTR + 2 * 64 * VSTR) * 4)

__global__ __launch_bounds__(256, 2)
void attn_mma2(const float* __restrict__ Q, const float* __restrict__ K,
               const float* __restrict__ V, float* __restrict__ O)
{
    extern __shared__ float sm[];
    const unsigned smb = (unsigned)__cvta_generic_to_shared(sm);

    const int qb   = blockIdx.x;
    const int hp   = blockIdx.y;
    const int b    = blockIdx.z;
    const int kvh  = hp >> 1;
    const int tid  = threadIdx.x;
    const int wid  = tid >> 5;
    const int lane = tid & 31;
    const int g    = lane >> 2;
    const int tg   = lane & 3;
    const int hsel = wid >> 2;
    const int head = 2 * hp + hsel;
    const int qrow0 = (wid & 3) * 16;

    const float scale = 0.125f;

    {
        const int hs2 = tid >> 7;
        const int tt  = tid & 127;
        const int qhead = 2 * hp + hs2;
        const unsigned qdst = smb + (hs2 ? OFF_PB : OFF_KB1) * 4;
        #pragma unroll
        for (int j = 0; j < 8; j++) {
            int idx = tt + j * 128;
            int r = idx >> 4, c = idx & 15;
            const float* src = Q + (size_t)(b * S_ + qb * 64 + r) * HID_ + qhead * HD_ + c * 4;
            CPA16(qdst + (r * KSTR + c * 4) * 4, src);
        }
        #pragma unroll
        for (int j = 0; j < 4; j++) {
            int idx = tid + j * 256;
            int r = idx >> 4, c = idx & 15;
            size_t gb = ((size_t)(b * S_ + r) * HKV_ + kvh) * HD_ + c * 4;
            CPA16(smb + (OFF_KB0 + r * KSTR + c * 4) * 4, K + gb);
            CPA16(smb + (OFF_VB0 + r * VSTR + c * 4) * 4, V + gb);
        }
        CPA_COMMIT();
        CPA_WAIT0();
    }
    __syncthreads();

    unsigned qfr[8][4];
    {
        const float* qsrc = sm + (hsel ? OFF_PB : OFF_KB1);
        #pragma unroll
        for (int kc = 0; kc < 8; kc++) {
            qfr[kc][0] = __float_as_uint(qsrc[(qrow0 + g    ) * KSTR + kc * 8 + tg    ]);
            qfr[kc][1] = __float_as_uint(qsrc[(qrow0 + g + 8) * KSTR + kc * 8 + tg    ]);
            qfr[kc][2] = __float_as_uint(qsrc[(qrow0 + g    ) * KSTR + kc * 8 + tg + 4]);
            qfr[kc][3] = __float_as_uint(qsrc[(qrow0 + g + 8) * KSTR + kc * 8 + tg + 4]);
        }
    }
    __syncthreads();

    float oacc[8][4];
    #pragma unroll
    for (int nt = 0; nt < 8; nt++)
        #pragma unroll
        for (int c = 0; c < 4; c++) oacc[nt][c] = 0.f;
    float m0 = -1e30f, m1 = -1e30f, l0 = 0.f, l1 = 0.f;

    const int qg0 = qb * 64 + qrow0 + g;
    const int qg1 = qg0 + 8;

    for (int kb = 0; kb <= qb; kb++) {
        const int s = kb & 1;
        const float* Kc = sm + (s ? OFF_KB1 : OFF_KB0);
        const float* Vc = sm + (s ? OFF_VB1 : OFF_VB0);

        if (kb < qb) {
            const int so = s ^ 1;
            #pragma unroll
            for (int j = 0; j < 4; j++) {
                int idx = tid + j * 256;
                int r = idx >> 4, c = idx & 15;
                size_t gb = ((size_t)(b * S_ + (kb + 1) * 64 + r) * HKV_ + kvh) * HD_ + c * 4;
                CPA16(smb + ((so ? OFF_KB1 : OFF_KB0) + r * KSTR + c * 4) * 4, K + gb);
                CPA16(smb + ((so ? OFF_VB1 : OFF_VB0) + r * VSTR + c * 4) * 4, V + gb);
            }
            CPA_COMMIT();
            CPA_WAIT1();
        } else {
            CPA_WAIT0();
        }
        __syncthreads();

        float sc[8][4];
        #pragma unroll
        for (int nt = 0; nt < 8; nt++) {
            sc[nt][0] = sc[nt][1] = sc[nt][2] = sc[nt][3] = 0.f;
            #pragma unroll
            for (int kc = 0; kc < 8; kc++) {
                unsigned b0 = __float_as_uint(Kc[(nt * 8 + g) * KSTR + kc * 8 + tg    ]);
                unsigned b1 = __float_as_uint(Kc[(nt * 8 + g) * KSTR + kc * 8 + tg + 4]);
                MMA_TF32(sc[nt], qfr[kc], b0, b1);
            }
        }

        const int kbase = kb * 64;
        #pragma unroll
        for (int nt = 0; nt < 8; nt++) {
            int key0 = kbase + nt * 8 + 2 * tg;
            sc[nt][0] = (key0     > qg0) ? -1e30f : sc[nt][0] * scale;
            sc[nt][1] = (key0 + 1 > qg0) ? -1e30f : sc[nt][1] * scale;
            sc[nt][2] = (key0     > qg1) ? -1e30f : sc[nt][2] * scale;
            sc[nt][3] = (key0 + 1 > qg1) ? -1e30f : sc[nt][3] * scale;
        }

        float mx0 = -1e30f, mx1 = -1e30f;
        #pragma unroll
        for (int nt = 0; nt < 8; nt++) {
            mx0 = fmaxf(mx0, fmaxf(sc[nt][0], sc[nt][1]));
            mx1 = fmaxf(mx1, fmaxf(sc[nt][2], sc[nt][3]));
        }
        mx0 = fmaxf(mx0, __shfl_xor_sync(0xffffffffu, mx0, 1));
        mx0 = fmaxf(mx0, __shfl_xor_sync(0xffffffffu, mx0, 2));
        mx1 = fmaxf(mx1, __shfl_xor_sync(0xffffffffu, mx1, 1));
        mx1 = fmaxf(mx1, __shfl_xor_sync(0xffffffffu, mx1, 2));

        float mn0 = fmaxf(m0, mx0), mn1 = fmaxf(m1, mx1);
        float cr0 = __expf(m0 - mn0), cr1 = __expf(m1 - mn1);
        l0 *= cr0; l1 *= cr1;
        #pragma unroll
        for (int nt = 0; nt < 8; nt++) {
            oacc[nt][0] *= cr0; oacc[nt][1] *= cr0;
            oacc[nt][2] *= cr1; oacc[nt][3] *= cr1;
        }
        m0 = mn0; m1 = mn1;

        __syncthreads();

        float* Pb = (float*)(hsel ? (sm + OFF_PB) : Kc);
        #pragma unroll
        for (int nt = 0; nt < 8; nt++) {
            float p00 = __expf(sc[nt][0] - m0);
            float p01 = __expf(sc[nt][1] - m0);
            float p10 = __expf(sc[nt][2] - m1);
            float p11 = __expf(sc[nt][3] - m1);
            l0 += p00 + p01;
            l1 += p10 + p11;
            int kcol = nt * 8 + 2 * tg;
            *(float2*)&Pb[(qrow0 + g    ) * KSTR + kcol] =
                make_float2(f2tf32f(p00), f2tf32f(p01));
            *(float2*)&Pb[(qrow0 + g + 8) * KSTR + kcol] =
                make_float2(f2tf32f(p10), f2tf32f(p11));
        }
        __syncwarp();

        #pragma unroll
        for (int kc = 0; kc < 8; kc++) {
            unsigned afr[4];
            afr[0] = __float_as_uint(Pb[(qrow0 + g    ) * KSTR + kc * 8 + tg    ]);
            afr[1] = __float_as_uint(Pb[(qrow0 + g + 8) * KSTR + kc * 8 + tg    ]);
            afr[2] = __float_as_uint(Pb[(qrow0 + g    ) * KSTR + kc * 8 + tg + 4]);
            afr[3] = __float_as_uint(Pb[(qrow0 + g + 8) * KSTR + kc * 8 + tg + 4]);
            #pragma unroll
            for (int nt = 0; nt < 8; nt++) {
                unsigned b0 = __float_as_uint(Vc[(kc * 8 + tg    ) * VSTR + nt * 8 + g]);
                unsigned b1 = __float_as_uint(Vc[(kc * 8 + tg + 4) * VSTR + nt * 8 + g]);
                MMA_TF32(oacc[nt], afr, b0, b1);
            }
        }
        __syncthreads();
    }

    l0 += __shfl_xor_sync(0xffffffffu, l0, 1);
    l0 += __shfl_xor_sync(0xffffffffu, l0, 2);
    l1 += __shfl_xor_sync(0xffffffffu, l1, 1);
    l1 += __shfl_xor_sync(0xffffffffu, l1, 2);
    float inv0 = 1.f / l0, inv1 = 1.f / l1;

    const size_t tok0 = (size_t)(b * S_ + qb * 64 + qrow0 + g);
    const size_t tok1 = tok0 + 8;
    #pragma unroll
    for (int nt = 0; nt < 8; nt++) {
        int col = head * HD_ + nt * 8 + 2 * tg;
        *(float2*)(O + tok0 * HID_ + col) =
            make_float2(f2tf32f(oacc[nt][0] * inv0), f2tf32f(oacc[nt][1] * inv0));
        *(float2*)(O + tok1 * HID_ + col) =
            make_float2(f2tf32f(oacc[nt][2] * inv1), f2tf32f(oacc[nt][3] * inv1));
    }
}

// ---------------------------------------------------------------------------
// Launch
// ---------------------------------------------------------------------------
extern "C" void kernel_launch(void* const* d_in, const int* in_sizes, int n_in,
                              void* d_out, int out_size)
{
    const float* hid  = (const float*)d_in[0];
    const float* cosT = (const float*)d_in[1];
    const float* sinT = (const float*)d_in[2];
    const float* Wq   = (const float*)d_in[3];
    const float* Wk   = (const float*)d_in[4];
    const float* Wv   = (const float*)d_in[5];
    const float* Wo   = (const float*)d_in[6];
    float* out = (float*)d_out;

    float *q_p, *k_p, *v_p, *attn_p, *rh_p, *wq_p, *wk_p, *wv_p, *wo_p;
    cudaGetSymbolAddress((void**)&q_p,    g_q);
    cudaGetSymbolAddress((void**)&k_p,    g_k);
    cudaGetSymbolAddress((void**)&v_p,    g_v);
    cudaGetSymbolAddress((void**)&attn_p, g_attn);
    cudaGetSymbolAddress((void**)&rh_p,   g_rh);
    cudaGetSymbolAddress((void**)&wq_p,   g_wq);
    cudaGetSymbolAddress((void**)&wk_p,   g_wk);
    cudaGetSymbolAddress((void**)&wv_p,   g_wv);
    cudaGetSymbolAddress((void**)&wo_p,   g_wo);

    cudaFuncSetAttribute(attn_mma2,
                         cudaFuncAttributeMaxDynamicSharedMemorySize, ATT_SMEM);
    cudaFuncSetAttribute(mma_gemm_pipe,
                         cudaFuncAttributeMaxDynamicSharedMemorySize, GEMM_SMEM);

    // Pre-round operands to tf32 (single launch)
    round_all_kernel<<<(SEG4 + 255) / 256, 256>>>(hid, Wq, Wk, Wv, Wo,
                                                  rh_p, wq_p, wk_p, wv_p, wo_p);

    // Fused QKV projection
    {
        dim3 g(24, 16);
        mma_gemm_pipe<<<g, 128, GEMM_SMEM>>>(rh_p, wq_p, wk_p, wv_p, q_p, k_p, v_p);
    }

    // RoPE (outputs tf32-rounded)
    {
        int totq = MTOK * HQ_ * 32;
        rope_kernel<<<(totq + 255) / 256, 256>>>(q_p, cosT, sinT, HQ_);
        int totk = MTOK * HKV_ * 32;
        rope_kernel<<<(totk + 255) / 256, 256>>>(k_p, cosT, sinT, HKV_);
    }

    // Attention
    {
        dim3 ga(S_ / 64, HQ_ / 2, B_);
        attn_mma2<<<ga, 256, ATT_SMEM>>>(q_p, k_p, v_p, attn_p);
    }

    // Output projection
    {
        dim3 go(16, 16);
        mma_gemm_pipe<<<go, 128, GEMM_SMEM>>>(attn_p, wo_p, wo_p, wo_p, out, out, out);
    }
}

// round 15
// speedup vs baseline: 2.7062x; 1.6193x over previous
#include <cuda_runtime.h>
#include <cuda_fp16.h>
#include <math.h>

// Problem constants
#define B_    2
#define S_    1024
#define HID_  2048
#define HQ_   32
#define HKV_  8
#define HD_   64
#define MTOK  (B_ * S_)

// Scratch (half precision)
__device__ __half g_q[MTOK * HID_];
__device__ __half g_k[MTOK * 512];
__device__ __half g_v[MTOK * 512];         // k-pair interleaved: [b][kvh][key2][d] half2
__device__ __half g_attn[MTOK * HID_];
__device__ __half g_rh[MTOK * HID_];
__device__ __half g_wq[HID_ * HID_];       // interleaved [k2][N] half2 words
__device__ __half g_wk[HID_ * 512];
__device__ __half g_wv[HID_ * 512];
__device__ __half g_wo[HID_ * HID_];

#define MMA_F16(D, A, B0, B1)                                               \
    asm volatile(                                                           \
        "mma.sync.aligned.m16n8k16.row.col.f32.f16.f16.f32 "                \
        "{%0,%1,%2,%3}, {%4,%5,%6,%7}, {%8,%9}, {%0,%1,%2,%3};"             \
        : "+f"((D)[0]), "+f"((D)[1]), "+f"((D)[2]), "+f"((D)[3])            \
        : "r"((A)[0]), "r"((A)[1]), "r"((A)[2]), "r"((A)[3]),               \
          "r"(B0), "r"(B1))

#define CPA16(smu32, gptr) \
    asm volatile("cp.async.cg.shared.global [%0], [%1], 16;" :: "r"(smu32), "l"(gptr))
#define CPA_COMMIT() asm volatile("cp.async.commit_group;")
#define CPA_WAIT0()  asm volatile("cp.async.wait_group 0;" ::: "memory")
#define CPA_WAIT1()  asm volatile("cp.async.wait_group 1;" ::: "memory")

__device__ __forceinline__ unsigned packh2(float lo, float hi) {
    __half2 h = __floats2half2_rn(lo, hi);   // .x = lo half, .y = hi half
    return *(unsigned*)&h;
}

// ---------------------------------------------------------------------------
// Pre-pass: hidden -> half (linear); weights -> half, k-pair interleaved:
//   out_word[k2*N + n] = half2(W[2k2][n], W[2k2+1][n])
// Segments (work units): hid 1M float4 | Wq 2M w | Wk .5M | Wv .5M | Wo 2M
// ---------------------------------------------------------------------------
#define CSEG0 (MTOK * HID_ / 4)
#define CSEG1 (CSEG0 + 1024 * 2048)
#define CSEG2 (CSEG1 + 1024 * 512)
#define CSEG3 (CSEG2 + 1024 * 512)
#define CSEG4 (CSEG3 + 1024 * 2048)

__global__ void convert_all_kernel(const float* __restrict__ hid,
                                   const float* __restrict__ Wq,
                                   const float* __restrict__ Wk,
                                   const float* __restrict__ Wv,
                                   const float* __restrict__ Wo)
{
    int i = blockIdx.x * blockDim.x + threadIdx.x;
    if (i >= CSEG4) return;
    if (i < CSEG0) {
        float4 v = ((const float4*)hid)[i];
        unsigned lo = packh2(v.x, v.y), hi = packh2(v.z, v.w);
        ((uint2*)g_rh)[i] = make_uint2(lo, hi);
        return;
    }
    const float* W; unsigned* dst; int j, N;
    if (i < CSEG1)      { W = Wq; dst = (unsigned*)g_wq; j = i - CSEG0; N = 2048; }
    else if (i < CSEG2) { W = Wk; dst = (unsigned*)g_wk; j = i - CSEG1; N = 512; }
    else if (i < CSEG3) { W = Wv; dst = (unsigned*)g_wv; j = i - CSEG2; N = 512; }
    else                { W = Wo; dst = (unsigned*)g_wo; j = i - CSEG3; N = 2048; }
    int k2 = j / N, n = j % N;
    dst[j] = packh2(W[(size_t)(2 * k2) * N + n], W[(size_t)(2 * k2 + 1) * N + n]);
}

// ---------------------------------------------------------------------------
// fp16 pipelined GEMM. A half [M][2048] (k contiguous), B interleaved words.
// CTA 128x128x32(k halfs), 128 thr (4 warps 2x2), warp tile 64x64, 3-stage.
// As: [128 rows][20 words] (16 data + 4 pad). Bs: [16 k2][136 words].
// outmode 0: fused QKV (bx split; Q/K half, V half interleaved)
// outmode 1: single GEMM, fp32 output.
// ---------------------------------------------------------------------------
#define GSTG  3
#define AW    20
#define BW    136
#define AS_W  (128 * AW)
#define BS_W  (16 * BW)
#define STG_W (AS_W + BS_W)
#define GEMM_SMEM (GSTG * STG_W * 4)
#define NKT   (HID_ / 32)

__global__ __launch_bounds__(128, 2)
void gemm_f16(const __half* __restrict__ A,
              const __half* __restrict__ Bq, const __half* __restrict__ Bk,
              const __half* __restrict__ Bv,
              __half* __restrict__ Cq, __half* __restrict__ Ck,
              float* __restrict__ Cf, int outmode)
{
    extern __shared__ unsigned smw[];
    const unsigned smb = (unsigned)__cvta_generic_to_shared(smw);

    const int bx = blockIdx.x;
    const int by = blockIdx.y;

    const __half* Bp; int Nb, n0, vmode = 0;
    __half* Ch = 0; float* Cfo = 0;
    if (outmode == 1) { Bp = Bq; Cfo = Cf; Nb = 2048; n0 = bx * 128; }
    else if (bx < 16)      { Bp = Bq; Ch = Cq; Nb = 2048; n0 = bx * 128; }
    else if (bx < 20) { Bp = Bk; Ch = Ck; Nb = 512;  n0 = (bx - 16) * 128; }
    else              { Bp = Bv; Nb = 512;  n0 = (bx - 20) * 128; vmode = 1; }

    const int tid  = threadIdx.x;
    const int wid  = tid >> 5;
    const int lane = tid & 31;
    const int wm   = wid >> 1;
    const int wn   = wid & 1;
    const int g    = lane >> 2;
    const int tg   = lane & 3;
    const int m0   = by * 128;

    float acc[4][8][4];
    #pragma unroll
    for (int mi = 0; mi < 4; mi++)
        #pragma unroll
        for (int ni = 0; ni < 8; ni++)
            #pragma unroll
            for (int c = 0; c < 4; c++) acc[mi][ni][c] = 0.f;

    const unsigned* Bw = (const unsigned*)Bp;   // interleaved words [k2][Nb]
    const int brow = tid >> 3;                  // 0..15
    const int bch  = tid & 7;                   // 16B chunk base

    auto load_tile = [&](int kt, int stg) {
        // A: thread -> row tid, 4 chunks of 16B (32 halfs)
        {
            const __half* ag = A + (size_t)(m0 + tid) * HID_ + kt * 32;
            unsigned as = smb + (stg * STG_W + tid * AW) * 4;
            #pragma unroll
            for (int j = 0; j < 4; j++)
                CPA16(as + j * 16, (const char*)ag + j * 16);
        }
        // B: row brow (k2), chunks bch + 8j  (row = 128 words = 512B)
        {
            const unsigned* bg = Bw + (size_t)(kt * 16 + brow) * Nb + n0;
            unsigned bs = smb + (stg * STG_W + AS_W + brow * BW) * 4;
            #pragma unroll
            for (int j = 0; j < 4; j++)
                CPA16(bs + (bch + 8 * j) * 16, (const char*)bg + (bch + 8 * j) * 16);
        }
        CPA_COMMIT();
    };

    load_tile(0, 0);
    load_tile(1, 1);

    for (int kt = 0; kt < NKT; kt++) {
        if (kt < NKT - 1) { CPA_WAIT1(); } else { CPA_WAIT0(); }
        __syncthreads();

        const unsigned* As_ = smw + (kt % GSTG) * STG_W;
        const unsigned* Bs_ = As_ + AS_W;

        #pragma unroll
        for (int ks = 0; ks < 2; ks++) {
            unsigned afr[4][4], bfr[8][2];
            #pragma unroll
            for (int mi = 0; mi < 4; mi++) {
                int mb = wm * 64 + mi * 16;
                afr[mi][0] = As_[(mb + g    ) * AW + ks * 8 + tg    ];
                afr[mi][1] = As_[(mb + g + 8) * AW + ks * 8 + tg    ];
                afr[mi][2] = As_[(mb + g    ) * AW + ks * 8 + tg + 4];
                afr[mi][3] = As_[(mb + g + 8) * AW + ks * 8 + tg + 4];
            }
            #pragma unroll
            for (int ni = 0; ni < 8; ni++) {
                int nb = wn * 64 + ni * 8;
                bfr[ni][0] = Bs_[(ks * 8 + tg    ) * BW + nb + g];
                bfr[ni][1] = Bs_[(ks * 8 + tg + 4) * BW + nb + g];
            }
            #pragma unroll
            for (int mi = 0; mi < 4; mi++)
                #pragma unroll
                for (int ni = 0; ni < 8; ni++)
                    MMA_F16(acc[mi][ni], afr[mi], bfr[ni][0], bfr[ni][1]);
        }
        __syncthreads();

        if (kt + 2 < NKT) load_tile(kt + 2, (kt + 2) % GSTG);
    }

    #pragma unroll
    for (int mi = 0; mi < 4; mi++) {
        int row0 = m0 + wm * 64 + mi * 16 + g;
        #pragma unroll
        for (int ni = 0; ni < 8; ni++) {
            int col = n0 + wn * 64 + ni * 8 + tg * 2;
            if (outmode == 1) {
                *(float2*)(Cfo + (size_t)row0 * Nb + col) =
                    make_float2(acc[mi][ni][0], acc[mi][ni][1]);
                *(float2*)(Cfo + (size_t)(row0 + 8) * Nb + col) =
                    make_float2(acc[mi][ni][2], acc[mi][ni][3]);
            } else if (!vmode) {
                *(unsigned*)(Ch + (size_t)row0 * Nb + col) =
                    packh2(acc[mi][ni][0], acc[mi][ni][1]);
                *(unsigned*)(Ch + (size_t)(row0 + 8) * Nb + col) =
                    packh2(acc[mi][ni][2], acc[mi][ni][3]);
            } else {
                // V interleaved: halfidx = ((bk*512 + s/2)*64 + d)*2 + (s&1)
                #pragma unroll
                for (int rr = 0; rr < 2; rr++) {
                    int tok = row0 + rr * 8;
                    int bb = tok >> 10, s = tok & 1023;
                    int kvh = col >> 6, d = col & 63;
                    size_t base = (((size_t)(bb * 8 + kvh) * 512 + (s >> 1)) * 64 + d) * 2 + (s & 1);
                    g_v[base]     = __float2half_rn(acc[mi][ni][rr * 2 + 0]);
                    g_v[base + 2] = __float2half_rn(acc[mi][ni][rr * 2 + 1]);
                }
            }
        }
    }
}

// ---------------------------------------------------------------------------
// RoPE (in place on half). X: (MTOK, nheads, 64).
// ---------------------------------------------------------------------------
__global__ void rope_kernel(__half* __restrict__ X,
                            const float* __restrict__ cosT,
                            const float* __restrict__ sinT,
                            int nheads)
{
    int idx = blockIdx.x * blockDim.x + threadIdx.x;
    int total = MTOK * nheads * 32;
    if (idx >= total) return;
    int d  = idx & 31;
    int hh = (idx >> 5) % nheads;
    int t  = idx / (32 * nheads);
    int s  = t & (S_ - 1);

    float c  = __ldg(cosT + s * HD_ + d);
    float sn = __ldg(sinT + s * HD_ + d);

    __half* base = X + ((size_t)t * nheads + hh) * HD_;
    float x0 = __half2float(base[d]);
    float x1 = __half2float(base[d + 32]);
    base[d]      = __float2half_rn(x0 * c - x1 * sn);
    base[d + 32] = __float2half_rn(x1 * c + x0 * sn);
}

// ---------------------------------------------------------------------------
// fp16 flash attention: 256 thr, 2 q-heads/CTA, double-buffered K/V cp.async.
// P stays in registers (C-frag layout == A-frag layout for fp16 k16).
// Q/K smem stride 36 words; V (key2-interleaved) stride 72 words.
// ---------------------------------------------------------------------------
#define QKW 36
#define VW  72
#define OFF_Q0 0
#define OFF_Q1 (64 * QKW)
#define OFF_K0 (2 * 64 * QKW)
#define OFF_K1 (3 * 64 * QKW)
#define OFF_V0 (4 * 64 * QKW)
#define OFF_V1 (4 * 64 * QKW + 32 * VW)
#define ATT_SMEM ((4 * 64 * QKW + 2 * 32 * VW) * 4)

__global__ __launch_bounds__(256, 2)
void attn_f16(const __half* __restrict__ Q, const __half* __restrict__ K,
              const __half* __restrict__ V, __half* __restrict__ O)
{
    extern __shared__ unsigned sw[];
    const unsigned smb = (unsigned)__cvta_generic_to_shared(sw);

    const int qb   = blockIdx.x;
    const int hp   = blockIdx.y;
    const int b    = blockIdx.z;
    const int kvh  = hp >> 1;
    const int tid  = threadIdx.x;
    const int wid  = tid >> 5;
    const int lane = tid & 31;
    const int g    = lane >> 2;
    const int tg   = lane & 3;
    const int hsel = wid >> 2;
    const int head = 2 * hp + hsel;
    const int qrow0 = (wid & 3) * 16;

    const float scale = 0.125f;
    const __half* Vbase = V + ((size_t)(b * 8 + kvh) * 512) * 128;  // [key2][128 halfs]

    // Prologue: Q (both heads) + K0 + V0
    {
        #pragma unroll
        for (int j = 0; j < 4; j++) {             // Q: 1024 chunks
            int c = tid + j * 256;
            int r = c >> 3, ch = c & 7;
            int hs = r >> 6, qr = r & 63;
            const __half* src = Q + (size_t)(b * S_ + qb * 64 + qr) * HID_
                                + (2 * hp + hs) * HD_ + ch * 8;
            CPA16(smb + ((hs ? OFF_Q1 : OFF_Q0) + qr * QKW) * 4 + ch * 16, src);
        }
        #pragma unroll
        for (int j = 0; j < 2; j++) {             // K0: 512 chunks
            int c = tid + j * 256;
            int r = c >> 3, ch = c & 7;
            const __half* src = K + (size_t)(b * S_ + r) * 512 + kvh * HD_ + ch * 8;
            CPA16(smb + (OFF_K0 + r * QKW) * 4 + ch * 16, src);
        }
        #pragma unroll
        for (int j = 0; j < 2; j++) {             // V0: 512 chunks
            int c = tid + j * 256;
            int r2 = c >> 4, ch = c & 15;
            CPA16(smb + (OFF_V0 + r2 * VW) * 4 + ch * 16, Vbase + r2 * 128 + ch * 8);
        }
        CPA_COMMIT();
        CPA_WAIT0();
    }
    __syncthreads();

    // Q fragments: qfr[kc][0..3], kc over 4 k16 steps of d
    unsigned qfr[4][4];
    {
        const unsigned* Qs = sw + (hsel ? OFF_Q1 : OFF_Q0);
        #pragma unroll
        for (int kc = 0; kc < 4; kc++) {
            qfr[kc][0] = Qs[(qrow0 + g    ) * QKW + 8 * kc + tg    ];
            qfr[kc][1] = Qs[(qrow0 + g + 8) * QKW + 8 * kc + tg    ];
            qfr[kc][2] = Qs[(qrow0 + g    ) * QKW + 8 * kc + tg + 4];
            qfr[kc][3] = Qs[(qrow0 + g + 8) * QKW + 8 * kc + tg + 4];
        }
    }

    float oacc[8][4];
    #pragma unroll
    for (int nt = 0; nt < 8; nt++)
        #pragma unroll
        for (int c = 0; c < 4; c++) oacc[nt][c] = 0.f;
    float m0 = -1e30f, m1 = -1e30f, l0 = 0.f, l1 = 0.f;

    const int qg0 = qb * 64 + qrow0 + g;
    const int qg1 = qg0 + 8;

    for (int kb = 0; kb <= qb; kb++) {
        const int s = kb & 1;
        const unsigned* Ks = sw + (s ? OFF_K1 : OFF_K0);
        const unsigned* Vs = sw + (s ? OFF_V1 : OFF_V0);

        if (kb < qb) {
            const int so = s ^ 1;
            #pragma unroll
            for (int j = 0; j < 2; j++) {
                int c = tid + j * 256;
                int r = c >> 3, ch = c & 7;
                const __half* src = K + (size_t)(b * S_ + (kb + 1) * 64 + r) * 512
                                    + kvh * HD_ + ch * 8;
                CPA16(smb + ((so ? OFF_K1 : OFF_K0) + r * QKW) * 4 + ch * 16, src);
            }
            #pragma unroll
            for (int j = 0; j < 2; j++) {
                int c = tid + j * 256;
                int r2 = c >> 4, ch = c & 15;
                CPA16(smb + ((so ? OFF_V1 : OFF_V0) + r2 * VW) * 4 + ch * 16,
                      Vbase + ((kb + 1) * 32 + r2) * 128 + ch * 8);
            }
            CPA_COMMIT();
            CPA_WAIT1();
        } else {
            CPA_WAIT0();
        }
        __syncthreads();

        // Scores S = Q K^T
        float sc[8][4];
        #pragma unroll
        for (int nt = 0; nt < 8; nt++) {
            sc[nt][0] = sc[nt][1] = sc[nt][2] = sc[nt][3] = 0.f;
            #pragma unroll
            for (int kc = 0; kc < 4; kc++) {
                unsigned b0 = Ks[(nt * 8 + g) * QKW + 8 * kc + tg    ];
                unsigned b1 = Ks[(nt * 8 + g) * QKW + 8 * kc + tg + 4];
                MMA_F16(sc[nt], qfr[kc], b0, b1);
            }
        }

        // Scale + causal mask
        const int kbase = kb * 64;
        #pragma unroll
        for (int nt = 0; nt < 8; nt++) {
            int key0 = kbase + nt * 8 + 2 * tg;
            sc[nt][0] = (key0     > qg0) ? -1e30f : sc[nt][0] * scale;
            sc[nt][1] = (key0 + 1 > qg0) ? -1e30f : sc[nt][1] * scale;
            sc[nt][2] = (key0     > qg1) ? -1e30f : sc[nt][2] * scale;
            sc[nt][3] = (key0 + 1 > qg1) ? -1e30f : sc[nt][3] * scale;
        }

        // Row max
        float mx0 = -1e30f, mx1 = -1e30f;
        #pragma unroll
        for (int nt = 0; nt < 8; nt++) {
            mx0 = fmaxf(mx0, fmaxf(sc[nt][0], sc[nt][1]));
            mx1 = fmaxf(mx1, fmaxf(sc[nt][2], sc[nt][3]));
        }
        mx0 = fmaxf(mx0, __shfl_xor_sync(0xffffffffu, mx0, 1));
        mx0 = fmaxf(mx0, __shfl_xor_sync(0xffffffffu, mx0, 2));
        mx1 = fmaxf(mx1, __shfl_xor_sync(0xffffffffu, mx1, 1));
        mx1 = fmaxf(mx1, __shfl_xor_sync(0xffffffffu, mx1, 2));

        float mn0 = fmaxf(m0, mx0), mn1 = fmaxf(m1, mx1);
        float cr0 = __expf(m0 - mn0), cr1 = __expf(m1 - mn1);
        l0 *= cr0; l1 *= cr1;
        #pragma unroll
        for (int nt = 0; nt < 8; nt++) {
            oacc[nt][0] *= cr0; oacc[nt][1] *= cr0;
            oacc[nt][2] *= cr1; oacc[nt][3] *= cr1;
        }
        m0 = mn0; m1 = mn1;

        // P in registers (C-frag -> A-frag identity), then PV
        float p[8][4];
        #pragma unroll
        for (int nt = 0; nt < 8; nt++) {
            p[nt][0] = __expf(sc[nt][0] - m0);
            p[nt][1] = __expf(sc[nt][1] - m0);
            p[nt][2] = __expf(sc[nt][2] - m1);
            p[nt][3] = __expf(sc[nt][3] - m1);
            l0 += p[nt][0] + p[nt][1];
            l1 += p[nt][2] + p[nt][3];
        }
        #pragma unroll
        for (int kc = 0; kc < 4; kc++) {
            unsigned afr[4];
            afr[0] = packh2(p[2 * kc    ][0], p[2 * kc    ][1]);
            afr[1] = packh2(p[2 * kc    ][2], p[2 * kc    ][3]);
            afr[2] = packh2(p[2 * kc + 1][0], p[2 * kc + 1][1]);
            afr[3] = packh2(p[2 * kc + 1][2], p[2 * kc + 1][3]);
            #pragma unroll
            for (int nt = 0; nt < 8; nt++) {
                unsigned b0 = Vs[(8 * kc + tg    ) * VW + nt * 8 + g];
                unsigned b1 = Vs[(8 * kc + tg + 4) * VW + nt * 8 + g];
                MMA_F16(oacc[nt], afr, b0, b1);
            }
        }
        __syncthreads();   // all warps done with Ks/Vs before next prefetch
    }

    l0 += __shfl_xor_sync(0xffffffffu, l0, 1);
    l0 += __shfl_xor_sync(0xffffffffu, l0, 2);
    l1 += __shfl_xor_sync(0xffffffffu, l1, 1);
    l1 += __shfl_xor_sync(0xffffffffu, l1, 2);
    float inv0 = 1.f / l0, inv1 = 1.f / l1;

    const size_t tok0 = (size_t)(b * S_ + qb * 64 + qrow0 + g);
    const size_t tok1 = tok0 + 8;
    #pragma unroll
    for (int nt = 0; nt < 8; nt++) {
        int col = head * HD_ + nt * 8 + 2 * tg;
        *(unsigned*)(O + tok0 * HID_ + col) =
            packh2(oacc[nt][0] * inv0, oacc[nt][1] * inv0);
        *(unsigned*)(O + tok1 * HID_ + col) =
            packh2(oacc[nt][2] * inv1, oacc[nt][3] * inv1);
    }
}

// ---------------------------------------------------------------------------
// Launch
// ---------------------------------------------------------------------------
extern "C" void kernel_launch(void* const* d_in, const int* in_sizes, int n_in,
                              void* d_out, int out_size)
{
    const float* hid  = (const float*)d_in[0];
    const float* cosT = (const float*)d_in[1];
    const float* sinT = (const float*)d_in[2];
    const float* Wq   = (const float*)d_in[3];
    const float* Wk   = (const float*)d_in[4];
    const float* Wv   = (const float*)d_in[5];
    const float* Wo   = (const float*)d_in[6];
    float* out = (float*)d_out;

    __half *q_p, *k_p, *v_p, *attn_p, *rh_p, *wq_p, *wk_p, *wv_p, *wo_p;
    cudaGetSymbolAddress((void**)&q_p,    g_q);
    cudaGetSymbolAddress((void**)&k_p,    g_k);
    cudaGetSymbolAddress((void**)&v_p,    g_v);
    cudaGetSymbolAddress((void**)&attn_p, g_attn);
    cudaGetSymbolAddress((void**)&rh_p,   g_rh);
    cudaGetSymbolAddress((void**)&wq_p,   g_wq);
    cudaGetSymbolAddress((void**)&wk_p,   g_wk);
    cudaGetSymbolAddress((void**)&wv_p,   g_wv);
    cudaGetSymbolAddress((void**)&wo_p,   g_wo);

    cudaFuncSetAttribute(attn_f16,
                         cudaFuncAttributeMaxDynamicSharedMemorySize, ATT_SMEM);
    cudaFuncSetAttribute(gemm_f16,
                         cudaFuncAttributeMaxDynamicSharedMemorySize, GEMM_SMEM);

    // Convert + interleave operands (single launch)
    convert_all_kernel<<<(CSEG4 + 255) / 256, 256>>>(hid, Wq, Wk, Wv, Wo);

    // Fused QKV projection (fp16)
    {
        dim3 g(24, 16);
        gemm_f16<<<g, 128, GEMM_SMEM>>>(rh_p, wq_p, wk_p, wv_p,
                                        q_p, k_p, (float*)0, 0);
    }

    // RoPE (half in place)
    {
        int totq = MTOK * HQ_ * 32;
        rope_kernel<<<(totq + 255) / 256, 256>>>(q_p, cosT, sinT, HQ_);
        int totk = MTOK * HKV_ * 32;
        rope_kernel<<<(totk + 255) / 256, 256>>>(k_p, cosT, sinT, HKV_);
    }

    // Attention (fp16, P register-resident)
    {
        dim3 ga(S_ / 64, HQ_ / 2, B_);
        attn_f16<<<ga, 256, ATT_SMEM>>>(q_p, k_p, v_p, attn_p);
    }

    // Output projection (fp16 inputs, fp32 output)
    {
        dim3 go(16, 16);
        gemm_f16<<<go, 128, GEMM_SMEM>>>(attn_p, wo_p, wo_p, wo_p,
                                         (__half*)0, (__half*)0, out, 1);
    }
}